// round 4
// baseline (speedup 1.0000x reference)
#include <cuda_runtime.h>

// ---------------------------------------------------------------------------
// SparseConvNet: masked 3D conv stack on 128^3 -> 64^3, then trilinear sample.
//
// Pipeline:
//   reset    : zero the compaction counter (graph-replay determinism)
//   prep     : g_x0 = x_feat * m0 (float4-packed), build active voxel list
//   maskdown : m1 = maxpool3x3x3(m0, stride 2, pad 1) on 64^3
//   conv0a   : 3->16 over active list only   (output gated by m0)
//   conv0b   : 16->16 over active list only
//   convd    : 16->32 stride-2 dense on 64^3 (gated by m1, 94% dense)
//   conv1a/b : 32->32 dense on 64^3
//   sample   : trilinear gather, warp-per-point, lane-per-channel
//
// Layout: all activation tensors are DHWC (channels innermost, float4 aligned).
// Weights staged into smem as [tap][ci][co] (co contiguous -> LDS.128).
// ---------------------------------------------------------------------------

#define D0   128
#define NV0  (D0 * D0 * D0)          // 2,097,152
#define D1   64
#define NV1  (D1 * D1 * D1)          // 262,144
#define NPTS 65536

// Scratch (device globals are zero-initialized at module load; voxels outside
// the mask are never written, so they stay zero -> matches reference gating).
__device__ float4 g_x0[NV0];                   //  33.5 MB masked input (3ch + pad)
__device__ float  g_h0a[(size_t)NV0 * 16];     // 134 MB
__device__ float  g_h0b[(size_t)NV0 * 16];     // 134 MB
__device__ float  g_h1a[(size_t)NV1 * 32];     //  33.5 MB
__device__ float  g_h1b[(size_t)NV1 * 32];
__device__ float  g_h1c[(size_t)NV1 * 32];
__device__ float  g_m1[NV1];
__device__ int    g_list0[NV0];
__device__ int    g_n0;

// ---------------------------------------------------------------------------
__global__ void reset_k() {
    if (threadIdx.x == 0) g_n0 = 0;
}

__global__ void prep_k(const float* __restrict__ x, const int* __restrict__ mask) {
    int v = blockIdx.x * blockDim.x + threadIdx.x;
    if (v >= NV0) return;
    int   m  = mask[v];
    float fm = (float)m;
    float a = x[v];
    float b = x[v + NV0];
    float c = x[v + 2 * NV0];
    g_x0[v] = make_float4(a * fm, b * fm, c * fm, 0.f);
    if (m) {
        int p = atomicAdd(&g_n0, 1);
        g_list0[p] = v;
    }
}

__global__ void maskdown_k(const int* __restrict__ mask) {
    int v = blockIdx.x * blockDim.x + threadIdx.x;
    if (v >= NV1) return;
    int x = v & 63, y = (v >> 6) & 63, z = v >> 12;
    int m = 0;
    for (int dz = 0; dz < 3; dz++) {
        int zi = 2 * z - 1 + dz;
        if ((unsigned)zi >= (unsigned)D0) continue;
        for (int dy = 0; dy < 3; dy++) {
            int yi = 2 * y - 1 + dy;
            if ((unsigned)yi >= (unsigned)D0) continue;
            for (int dx = 0; dx < 3; dx++) {
                int xi = 2 * x - 1 + dx;
                if ((unsigned)xi >= (unsigned)D0) continue;
                if (mask[((size_t)((zi << 7) + yi) << 7) + xi] != 0) m = 1;
            }
        }
    }
    g_m1[v] = (float)m;
}

// ---------------------------------------------------------------------------
// Sparse conv over the compacted active-voxel list (layer 0). Input/output on
// the 128^3 grid, DHWC. CIN is the padded channel count (float4 multiple),
// CINR the real one (weights for padded channels staged as 0).
// ---------------------------------------------------------------------------
template <int CIN, int CINR, int COUT>
__device__ __forceinline__ void conv_sparse_body(
    const float* __restrict__ in, const float* __restrict__ w,
    const float* __restrict__ scale, const float* __restrict__ shift,
    float* __restrict__ out)
{
    constexpr int G = COUT / 4;
    __shared__ float ws[27 * CIN * COUT];
    __shared__ float ssc[COUT], ssh[COUT];

    // Whole-block early exit (uniform) before staging: ~90% of blocks bail.
    if (blockIdx.x * blockDim.x >= g_n0) return;

    for (int i = threadIdx.x; i < 27 * CIN * COUT; i += blockDim.x) {
        int co  = i % COUT;
        int rem = i / COUT;
        int ci  = rem % CIN;
        int tap = rem / CIN;
        ws[i] = (ci < CINR) ? w[((size_t)co * CINR + ci) * 27 + tap] : 0.f;
    }
    if (threadIdx.x < COUT) {
        ssc[threadIdx.x] = scale[threadIdx.x];
        ssh[threadIdx.x] = shift[threadIdx.x];
    }
    __syncthreads();

    int i = blockIdx.x * blockDim.x + threadIdx.x;
    if (i >= g_n0) return;
    int v = g_list0[i];
    int x = v & (D0 - 1), y = (v >> 7) & (D0 - 1), z = v >> 14;

    float acc[COUT];
#pragma unroll
    for (int c = 0; c < COUT; c++) acc[c] = 0.f;

#pragma unroll 1
    for (int dz = 0; dz < 3; dz++) {
        int zi = z - 1 + dz;
        if ((unsigned)zi >= (unsigned)D0) continue;
#pragma unroll 1
        for (int dy = 0; dy < 3; dy++) {
            int yi = y - 1 + dy;
            if ((unsigned)yi >= (unsigned)D0) continue;
#pragma unroll 1
            for (int dx = 0; dx < 3; dx++) {
                int xi = x - 1 + dx;
                if ((unsigned)xi >= (unsigned)D0) continue;
                const float4* ip =
                    (const float4*)(in + ((size_t)((zi << 7) + yi) * D0 + xi) * CIN);
                const float* wt = ws + ((dz * 3 + dy) * 3 + dx) * CIN * COUT;
#pragma unroll
                for (int c4 = 0; c4 < CIN / 4; c4++) {
                    float4 iv = ip[c4];
                    float  a4[4] = {iv.x, iv.y, iv.z, iv.w};
#pragma unroll
                    for (int j = 0; j < 4; j++) {
                        const float4* wq = (const float4*)(wt + (c4 * 4 + j) * COUT);
                        float a = a4[j];
#pragma unroll
                        for (int g = 0; g < G; g++) {
                            float4 wv = wq[g];
                            acc[4 * g + 0] += a * wv.x;
                            acc[4 * g + 1] += a * wv.y;
                            acc[4 * g + 2] += a * wv.z;
                            acc[4 * g + 3] += a * wv.w;
                        }
                    }
                }
            }
        }
    }

    float4* op = (float4*)(out + (size_t)v * COUT);
#pragma unroll
    for (int g = 0; g < G; g++) {
        float4 r;
        r.x = fmaxf(acc[4 * g + 0] * ssc[4 * g + 0] + ssh[4 * g + 0], 0.f);
        r.y = fmaxf(acc[4 * g + 1] * ssc[4 * g + 1] + ssh[4 * g + 1], 0.f);
        r.z = fmaxf(acc[4 * g + 2] * ssc[4 * g + 2] + ssh[4 * g + 2], 0.f);
        r.w = fmaxf(acc[4 * g + 3] * ssc[4 * g + 3] + ssh[4 * g + 3], 0.f);
        op[g] = r;
    }
}

// ---------------------------------------------------------------------------
// Dense conv on the 64^3 output grid (downsample / layer 1). Each block
// computes COUT_T of coutTotal output channels (blockIdx.y selects group).
// ---------------------------------------------------------------------------
template <int CIN, int COUT_T, int STRIDE, int DIN, int DOUT>
__device__ __forceinline__ void conv_dense_body(
    const float* __restrict__ in, const float* __restrict__ w,
    const float* __restrict__ scale, const float* __restrict__ shift,
    const float* __restrict__ msk, float* __restrict__ out, int coutTotal)
{
    constexpr int G = COUT_T / 4;
    __shared__ float ws[27 * CIN * COUT_T];
    __shared__ float ssc[COUT_T], ssh[COUT_T];

    int coBase = blockIdx.y * COUT_T;
    for (int i = threadIdx.x; i < 27 * CIN * COUT_T; i += blockDim.x) {
        int co  = i % COUT_T;
        int rem = i / COUT_T;
        int ci  = rem % CIN;
        int tap = rem / CIN;
        ws[i] = w[((size_t)(coBase + co) * CIN + ci) * 27 + tap];
    }
    if (threadIdx.x < COUT_T) {
        ssc[threadIdx.x] = scale[coBase + threadIdx.x];
        ssh[threadIdx.x] = shift[coBase + threadIdx.x];
    }
    __syncthreads();

    int v = blockIdx.x * blockDim.x + threadIdx.x;
    int x = v % DOUT, y = (v / DOUT) % DOUT, z = v / (DOUT * DOUT);

    float acc[COUT_T];
#pragma unroll
    for (int c = 0; c < COUT_T; c++) acc[c] = 0.f;

#pragma unroll 1
    for (int dz = 0; dz < 3; dz++) {
        int zi = z * STRIDE - 1 + dz;
        if ((unsigned)zi >= (unsigned)DIN) continue;
#pragma unroll 1
        for (int dy = 0; dy < 3; dy++) {
            int yi = y * STRIDE - 1 + dy;
            if ((unsigned)yi >= (unsigned)DIN) continue;
#pragma unroll 1
            for (int dx = 0; dx < 3; dx++) {
                int xi = x * STRIDE - 1 + dx;
                if ((unsigned)xi >= (unsigned)DIN) continue;
                const float4* ip =
                    (const float4*)(in + ((size_t)(zi * DIN + yi) * DIN + xi) * CIN);
                const float* wt = ws + ((dz * 3 + dy) * 3 + dx) * CIN * COUT_T;
#pragma unroll
                for (int c4 = 0; c4 < CIN / 4; c4++) {
                    float4 iv = ip[c4];
                    float  a4[4] = {iv.x, iv.y, iv.z, iv.w};
#pragma unroll
                    for (int j = 0; j < 4; j++) {
                        const float4* wq = (const float4*)(wt + (c4 * 4 + j) * COUT_T);
                        float a = a4[j];
#pragma unroll
                        for (int g = 0; g < G; g++) {
                            float4 wv = wq[g];
                            acc[4 * g + 0] += a * wv.x;
                            acc[4 * g + 1] += a * wv.y;
                            acc[4 * g + 2] += a * wv.z;
                            acc[4 * g + 3] += a * wv.w;
                        }
                    }
                }
            }
        }
    }

    float mm = msk[v];
    float4* op = (float4*)(out + (size_t)v * coutTotal + coBase);
#pragma unroll
    for (int g = 0; g < G; g++) {
        float4 r;
        r.x = fmaxf(acc[4 * g + 0] * ssc[4 * g + 0] + ssh[4 * g + 0], 0.f) * mm;
        r.y = fmaxf(acc[4 * g + 1] * ssc[4 * g + 1] + ssh[4 * g + 1], 0.f) * mm;
        r.z = fmaxf(acc[4 * g + 2] * ssc[4 * g + 2] + ssh[4 * g + 2], 0.f) * mm;
        r.w = fmaxf(acc[4 * g + 3] * ssc[4 * g + 3] + ssh[4 * g + 3], 0.f) * mm;
        op[g] = r;
    }
}

// ---------------------------------------------------------------------------
__global__ void conv0a_k(const float* w, const float* s, const float* b) {
    conv_sparse_body<4, 3, 16>((const float*)g_x0, w, s, b, g_h0a);
}
__global__ void conv0b_k(const float* w, const float* s, const float* b) {
    conv_sparse_body<16, 16, 16>(g_h0a, w, s, b, g_h0b);
}
__global__ void convd_k(const float* w, const float* s, const float* b) {
    conv_dense_body<16, 8, 2, 128, 64>(g_h0b, w, s, b, g_m1, g_h1a, 32);
}
__global__ void conv1a_k(const float* w, const float* s, const float* b) {
    conv_dense_body<32, 8, 1, 64, 64>(g_h1a, w, s, b, g_m1, g_h1b, 32);
}
__global__ void conv1b_k(const float* w, const float* s, const float* b) {
    conv_dense_body<32, 8, 1, 64, 64>(g_h1b, w, s, b, g_m1, g_h1c, 32);
}

// ---------------------------------------------------------------------------
// Trilinear sampling: one warp per point, one lane per channel.
// ---------------------------------------------------------------------------
__global__ void sample_k(const float* __restrict__ coords, float* __restrict__ out) {
    int t = blockIdx.x * blockDim.x + threadIdx.x;
    if (t >= NPTS * 32) return;
    int p = t >> 5, lane = t & 31;

    float cx = coords[3 * p + 0];
    float cy = coords[3 * p + 1];
    float cz = coords[3 * p + 2];
    float fx = (cx + 1.f) * 0.5f * (float)(D1 - 1);
    float fy = (cy + 1.f) * 0.5f * (float)(D1 - 1);
    float fz = (cz + 1.f) * 0.5f * (float)(D1 - 1);
    float x0f = floorf(fx), y0f = floorf(fy), z0f = floorf(fz);
    float tx = fx - x0f, ty = fy - y0f, tz = fz - z0f;
    int x0 = (int)x0f, y0 = (int)y0f, z0 = (int)z0f;

    float acc = 0.f;
#pragma unroll
    for (int dz = 0; dz < 2; dz++) {
#pragma unroll
        for (int dy = 0; dy < 2; dy++) {
#pragma unroll
            for (int dx = 0; dx < 2; dx++) {
                int xi = x0 + dx, yi = y0 + dy, zi = z0 + dz;
                bool valid = (xi >= 0) && (xi < D1) && (yi >= 0) && (yi < D1) &&
                             (zi >= 0) && (zi < D1);
                float wgt = (dx ? tx : 1.f - tx) * (dy ? ty : 1.f - ty) *
                            (dz ? tz : 1.f - tz);
                int xc = min(max(xi, 0), D1 - 1);
                int yc = min(max(yi, 0), D1 - 1);
                int zc = min(max(zi, 0), D1 - 1);
                float val = g_h1c[((size_t)((zc << 6) + yc) * D1 + xc) * 32 + lane];
                acc += val * (valid ? wgt : 0.f);
            }
        }
    }
    out[(size_t)p * 32 + lane] = acc;
}

// ---------------------------------------------------------------------------
extern "C" void kernel_launch(void* const* d_in, const int* in_sizes, int n_in,
                              void* d_out, int out_size) {
    const float* x_feat = (const float*)d_in[0];
    const int*   mask   = (const int*)d_in[1];
    const float* coords = (const float*)d_in[2];
    const float* w0a = (const float*)d_in[3];
    const float* s0a = (const float*)d_in[4];
    const float* b0a = (const float*)d_in[5];
    const float* w0b = (const float*)d_in[6];
    const float* s0b = (const float*)d_in[7];
    const float* b0b = (const float*)d_in[8];
    const float* wd0 = (const float*)d_in[9];
    const float* sd0 = (const float*)d_in[10];
    const float* bd0 = (const float*)d_in[11];
    const float* w1a = (const float*)d_in[12];
    const float* s1a = (const float*)d_in[13];
    const float* b1a = (const float*)d_in[14];
    const float* w1b = (const float*)d_in[15];
    const float* s1b = (const float*)d_in[16];
    const float* b1b = (const float*)d_in[17];
    float* out = (float*)d_out;

    reset_k<<<1, 32>>>();
    prep_k<<<NV0 / 256, 256>>>(x_feat, mask);
    maskdown_k<<<NV1 / 256, 256>>>(mask);
    conv0a_k<<<NV0 / 128, 128>>>(w0a, s0a, b0a);
    conv0b_k<<<NV0 / 128, 128>>>(w0b, s0b, b0b);
    convd_k<<<dim3(NV1 / 128, 4), 128>>>(wd0, sd0, bd0);
    conv1a_k<<<dim3(NV1 / 128, 4), 128>>>(w1a, s1a, b1a);
    conv1b_k<<<dim3(NV1 / 128, 4), 128>>>(w1b, s1b, b1b);
    sample_k<<<(NPTS * 32) / 256, 256>>>(coords, out);
}

// round 6
// speedup vs baseline: 2.3310x; 2.3310x over previous
#include <cuda_runtime.h>

// ---------------------------------------------------------------------------
// SparseConvNet: masked 3D conv stack on 128^3 -> 64^3, then trilinear sample.
//
//   reset    : zero compaction counter
//   prep     : g_x0 = x_feat * m0 (float4 DHWC), build active voxel list
//   maskdown : m1 = maxpool3x3x3 stride2
//   wtr x5   : weights -> [tap][ci][co], bn scale folded in, ci padded
//   conv0a/b : sparse (active-list) convs on 128^3
//   convd    : 16->32 stride-2, smem-row-staged dense conv -> 64^3
//   conv1a/b : 32->32 smem-row-staged dense convs on 64^3
//   sample   : trilinear gather, lane = channel
//
// Dense conv: block = one output x-row (64 voxels) x 32 couts, 128 threads
// (thread = (x, co-half)). Input rows staged to smem TRANSPOSED [ci][x] via
// coalesced copy -> kills the 32-wavefront-per-LDG L1 pathology of DHWC
// per-thread-voxel loads. Compute is conflict-free LDS + FFMA.
// ---------------------------------------------------------------------------

#define D0   128
#define NV0  (D0 * D0 * D0)
#define D1   64
#define NV1  (D1 * D1 * D1)
#define NPTS 65536

__device__ float4 g_x0[NV0];
__device__ float  g_h0a[(size_t)NV0 * 16];
__device__ float  g_h0b[(size_t)NV0 * 16];
__device__ float  g_h1a[(size_t)NV1 * 32];
__device__ float  g_h1b[(size_t)NV1 * 32];
__device__ float  g_h1c[(size_t)NV1 * 32];
__device__ float  g_m1[NV1];
__device__ int    g_list0[NV0];
__device__ int    g_n0;

// Pre-transposed weights: [tap][ci][co], scale folded, ci zero-padded.
__device__ float g_wt0a[27 * 4 * 16];
__device__ float g_wt0b[27 * 16 * 16];
__device__ float g_wtd [27 * 16 * 32];
__device__ float g_wt1a[27 * 32 * 32];
__device__ float g_wt1b[27 * 32 * 32];

// ---------------------------------------------------------------------------
__global__ void reset_k() {
    if (threadIdx.x == 0) g_n0 = 0;
}

__global__ void prep_k(const float* __restrict__ x, const int* __restrict__ mask) {
    int v = blockIdx.x * blockDim.x + threadIdx.x;
    if (v >= NV0) return;
    int   m  = mask[v];
    float fm = (float)m;
    float a = x[v];
    float b = x[v + NV0];
    float c = x[v + 2 * NV0];
    g_x0[v] = make_float4(a * fm, b * fm, c * fm, 0.f);
    if (m) {
        int p = atomicAdd(&g_n0, 1);
        g_list0[p] = v;
    }
}

__global__ void maskdown_k(const int* __restrict__ mask) {
    int v = blockIdx.x * blockDim.x + threadIdx.x;
    if (v >= NV1) return;
    int x = v & 63, y = (v >> 6) & 63, z = v >> 12;
    int m = 0;
    for (int dz = 0; dz < 3; dz++) {
        int zi = 2 * z - 1 + dz;
        if ((unsigned)zi >= (unsigned)D0) continue;
        for (int dy = 0; dy < 3; dy++) {
            int yi = 2 * y - 1 + dy;
            if ((unsigned)yi >= (unsigned)D0) continue;
            for (int dx = 0; dx < 3; dx++) {
                int xi = 2 * x - 1 + dx;
                if ((unsigned)xi >= (unsigned)D0) continue;
                if (mask[((size_t)((zi << 7) + yi) << 7) + xi] != 0) m = 1;
            }
        }
    }
    g_m1[v] = (float)m;
}

// Weight transpose + bn-scale fold: dst[tap][ci][co], padded ci -> 0.
__global__ void wtr_k(const float* __restrict__ src, const float* __restrict__ scale,
                      float* __restrict__ dst, int CINR, int CIN, int COUT) {
    int i = blockIdx.x * blockDim.x + threadIdx.x;
    int total = 27 * CIN * COUT;
    if (i >= total) return;
    int co  = i % COUT;
    int rem = i / COUT;
    int ci  = rem % CIN;
    int tap = rem / CIN;
    dst[i] = (ci < CINR) ? src[((size_t)co * CINR + ci) * 27 + tap] * scale[co] : 0.f;
}

// ---------------------------------------------------------------------------
// Sparse conv over the compacted active-voxel list (layer 0), 128^3 DHWC.
// ---------------------------------------------------------------------------
template <int CIN, int COUT>
__device__ __forceinline__ void conv_sparse_body(
    const float* __restrict__ in, const float* __restrict__ wt,
    const float* __restrict__ shift, float* __restrict__ out)
{
    constexpr int G = COUT / 4;
    __shared__ float ws[27 * CIN * COUT];
    __shared__ float ssh[COUT];

    if (blockIdx.x * blockDim.x >= g_n0) return;   // block-uniform early exit

    for (int i = threadIdx.x; i < 27 * CIN * COUT; i += blockDim.x)
        ws[i] = wt[i];                              // coalesced contiguous copy
    if (threadIdx.x < COUT) ssh[threadIdx.x] = shift[threadIdx.x];
    __syncthreads();

    int i = blockIdx.x * blockDim.x + threadIdx.x;
    if (i >= g_n0) return;
    int v = g_list0[i];
    int x = v & (D0 - 1), y = (v >> 7) & (D0 - 1), z = v >> 14;

    float acc[COUT];
#pragma unroll
    for (int c = 0; c < COUT; c++) acc[c] = 0.f;

#pragma unroll 1
    for (int dz = 0; dz < 3; dz++) {
        int zi = z - 1 + dz;
        if ((unsigned)zi >= (unsigned)D0) continue;
#pragma unroll 1
        for (int dy = 0; dy < 3; dy++) {
            int yi = y - 1 + dy;
            if ((unsigned)yi >= (unsigned)D0) continue;
#pragma unroll 1
            for (int dx = 0; dx < 3; dx++) {
                int xi = x - 1 + dx;
                if ((unsigned)xi >= (unsigned)D0) continue;
                const float4* ip =
                    (const float4*)(in + ((size_t)((zi << 7) + yi) * D0 + xi) * CIN);
                const float* wtap = ws + ((dz * 3 + dy) * 3 + dx) * CIN * COUT;
#pragma unroll
                for (int c4 = 0; c4 < CIN / 4; c4++) {
                    float4 iv = ip[c4];
                    float  a4[4] = {iv.x, iv.y, iv.z, iv.w};
#pragma unroll
                    for (int j = 0; j < 4; j++) {
                        const float4* wq = (const float4*)(wtap + (c4 * 4 + j) * COUT);
                        float a = a4[j];
#pragma unroll
                        for (int g = 0; g < G; g++) {
                            float4 wv = wq[g];
                            acc[4 * g + 0] += a * wv.x;
                            acc[4 * g + 1] += a * wv.y;
                            acc[4 * g + 2] += a * wv.z;
                            acc[4 * g + 3] += a * wv.w;
                        }
                    }
                }
            }
        }
    }

    float4* op = (float4*)(out + (size_t)v * COUT);
#pragma unroll
    for (int g = 0; g < G; g++) {
        float4 r;
        r.x = fmaxf(acc[4 * g + 0] + ssh[4 * g + 0], 0.f);
        r.y = fmaxf(acc[4 * g + 1] + ssh[4 * g + 1], 0.f);
        r.z = fmaxf(acc[4 * g + 2] + ssh[4 * g + 2], 0.f);
        r.w = fmaxf(acc[4 * g + 3] + ssh[4 * g + 3], 0.f);
        op[g] = r;
    }
}

__global__ void conv0a_k(const float* shift) {
    conv_sparse_body<4, 16>((const float*)g_x0, g_wt0a, shift, g_h0a);
}
__global__ void conv0b_k(const float* shift) {
    conv_sparse_body<16, 16>(g_h0a, g_wt0b, shift, g_h0b);
}

// ---------------------------------------------------------------------------
// Dense smem-row-staged conv onto the 64^3 grid. COUT=32.
// Block = one output x-row; thread = (x in 0..63, co-half in 0..1), acc[16].
// ---------------------------------------------------------------------------
template <int CIN, int STRIDE, int DIN>
__global__ void __launch_bounds__(128)
conv_dense2_k(const float* __restrict__ in, const float* __restrict__ wt,
              const float* __restrict__ shift, float* __restrict__ out)
{
    constexpr int DOUT = 64;
    constexpr int COUT = 32;
    constexpr int COH  = 16;
    constexpr int XW   = (STRIDE == 1) ? 66 : 129;   // staged row width (with halo)
    constexpr int XPAD = (STRIDE == 1) ? 67 : 133;   // coprime-32 pad -> no STS conflicts

    __shared__ float s_in[CIN * XPAD];
    __shared__ float s_w[3 * CIN * COUT];
    __shared__ float s_sh[COUT];

    int b = blockIdx.x;
    int y = b & 63, z = b >> 6;
    int tid = threadIdx.x;
    int x = tid & 63;
    int coh = tid >> 6;
    int coBase = coh * COH;

    if (tid < COUT) s_sh[tid] = shift[tid];

    float acc[COH];
#pragma unroll
    for (int k = 0; k < COH; k++) acc[k] = 0.f;

#pragma unroll 1
    for (int dz = 0; dz < 3; dz++) {
        int zi = z * STRIDE - 1 + dz;
        if ((unsigned)zi >= (unsigned)DIN) continue;
#pragma unroll 1
        for (int dy = 0; dy < 3; dy++) {
            int yi = y * STRIDE - 1 + dy;
            if ((unsigned)yi >= (unsigned)DIN) continue;   // block-uniform: skip row

            __syncthreads();   // previous compute done with s_in/s_w
            {
                // Stage input row transposed: s_in[ci][xi+1], coalesced global reads.
                const float* rp = in + (size_t)(zi * DIN + yi) * DIN * CIN;
                for (int i = tid; i < XW * CIN; i += 128) {
                    int xi = i / CIN - 1;
                    int ci = i & (CIN - 1);
                    float v = ((unsigned)xi < (unsigned)DIN) ? rp[(size_t)xi * CIN + ci] : 0.f;
                    s_in[ci * XPAD + (xi + 1)] = v;
                }
                // Stage 3 x-taps of weights: contiguous copy from [tap][ci][co].
                const float* wp = wt + (size_t)((dz * 3 + dy) * 3) * CIN * COUT;
                for (int i = tid; i < 3 * CIN * COUT; i += 128) s_w[i] = wp[i];
            }
            __syncthreads();

            int xb = x * STRIDE;   // s_in slot of xi = x*STRIDE-1
#pragma unroll 4
            for (int ci = 0; ci < CIN; ci++) {
                float a0 = s_in[ci * XPAD + xb + 0];
                float a1 = s_in[ci * XPAD + xb + 1];
                float a2 = s_in[ci * XPAD + xb + 2];
                const float4* w0 = (const float4*)(s_w + (0 * CIN + ci) * COUT + coBase);
                const float4* w1 = (const float4*)(s_w + (1 * CIN + ci) * COUT + coBase);
                const float4* w2 = (const float4*)(s_w + (2 * CIN + ci) * COUT + coBase);
#pragma unroll
                for (int g = 0; g < COH / 4; g++) {
                    float4 v0 = w0[g], v1 = w1[g], v2 = w2[g];
                    acc[4 * g + 0] += a0 * v0.x + a1 * v1.x + a2 * v2.x;
                    acc[4 * g + 1] += a0 * v0.y + a1 * v1.y + a2 * v2.y;
                    acc[4 * g + 2] += a0 * v0.z + a1 * v1.z + a2 * v2.z;
                    acc[4 * g + 3] += a0 * v0.w + a1 * v1.w + a2 * v2.w;
                }
            }
        }
    }

    size_t v = (size_t)(z * DOUT + y) * DOUT + x;
    float  m = g_m1[v];
    float4* op = (float4*)(out + v * COUT + coBase);
#pragma unroll
    for (int g = 0; g < COH / 4; g++) {
        float4 r;
        r.x = fmaxf(acc[4 * g + 0] + s_sh[coBase + 4 * g + 0], 0.f) * m;
        r.y = fmaxf(acc[4 * g + 1] + s_sh[coBase + 4 * g + 1], 0.f) * m;
        r.z = fmaxf(acc[4 * g + 2] + s_sh[coBase + 4 * g + 2], 0.f) * m;
        r.w = fmaxf(acc[4 * g + 3] + s_sh[coBase + 4 * g + 3], 0.f) * m;
        op[g] = r;
    }
}

// ---------------------------------------------------------------------------
// Trilinear sampling: lane = channel (coalesced 128B per corner fetch).
// ---------------------------------------------------------------------------
__global__ void sample_k(const float* __restrict__ coords, float* __restrict__ out) {
    int t = blockIdx.x * blockDim.x + threadIdx.x;
    if (t >= NPTS * 32) return;
    int p = t >> 5, lane = t & 31;

    float cx = coords[3 * p + 0];
    float cy = coords[3 * p + 1];
    float cz = coords[3 * p + 2];
    float fx = (cx + 1.f) * 0.5f * (float)(D1 - 1);
    float fy = (cy + 1.f) * 0.5f * (float)(D1 - 1);
    float fz = (cz + 1.f) * 0.5f * (float)(D1 - 1);
    float x0f = floorf(fx), y0f = floorf(fy), z0f = floorf(fz);
    float tx = fx - x0f, ty = fy - y0f, tz = fz - z0f;
    int x0 = (int)x0f, y0 = (int)y0f, z0 = (int)z0f;

    float acc = 0.f;
#pragma unroll
    for (int dz = 0; dz < 2; dz++) {
#pragma unroll
        for (int dy = 0; dy < 2; dy++) {
#pragma unroll
            for (int dx = 0; dx < 2; dx++) {
                int xi = x0 + dx, yi = y0 + dy, zi = z0 + dz;
                bool valid = (xi >= 0) && (xi < D1) && (yi >= 0) && (yi < D1) &&
                             (zi >= 0) && (zi < D1);
                float wgt = (dx ? tx : 1.f - tx) * (dy ? ty : 1.f - ty) *
                            (dz ? tz : 1.f - tz);
                int xc = min(max(xi, 0), D1 - 1);
                int yc = min(max(yi, 0), D1 - 1);
                int zc = min(max(zi, 0), D1 - 1);
                float val = g_h1c[((size_t)((zc << 6) + yc) * D1 + xc) * 32 + lane];
                acc += val * (valid ? wgt : 0.f);
            }
        }
    }
    out[(size_t)p * 32 + lane] = acc;
}

// ---------------------------------------------------------------------------
extern "C" void kernel_launch(void* const* d_in, const int* in_sizes, int n_in,
                              void* d_out, int out_size) {
    const float* x_feat = (const float*)d_in[0];
    const int*   mask   = (const int*)d_in[1];
    const float* coords = (const float*)d_in[2];
    const float* w0a = (const float*)d_in[3];
    const float* s0a = (const float*)d_in[4];
    const float* b0a = (const float*)d_in[5];
    const float* w0b = (const float*)d_in[6];
    const float* s0b = (const float*)d_in[7];
    const float* b0b = (const float*)d_in[8];
    const float* wd0 = (const float*)d_in[9];
    const float* sd0 = (const float*)d_in[10];
    const float* bd0 = (const float*)d_in[11];
    const float* w1a = (const float*)d_in[12];
    const float* s1a = (const float*)d_in[13];
    const float* b1a = (const float*)d_in[14];
    const float* w1b = (const float*)d_in[15];
    const float* s1b = (const float*)d_in[16];
    const float* b1b = (const float*)d_in[17];
    float* out = (float*)d_out;

    float* wt0a; cudaGetSymbolAddress((void**)&wt0a, g_wt0a);
    float* wt0b; cudaGetSymbolAddress((void**)&wt0b, g_wt0b);
    float* wtd;  cudaGetSymbolAddress((void**)&wtd,  g_wtd);
    float* wt1a; cudaGetSymbolAddress((void**)&wt1a, g_wt1a);
    float* wt1b; cudaGetSymbolAddress((void**)&wt1b, g_wt1b);
    float* h0b;  cudaGetSymbolAddress((void**)&h0b,  g_h0b);
    float* h1a;  cudaGetSymbolAddress((void**)&h1a,  g_h1a);
    float* h1b;  cudaGetSymbolAddress((void**)&h1b,  g_h1b);
    float* h1c;  cudaGetSymbolAddress((void**)&h1c,  g_h1c);

    reset_k<<<1, 32>>>();
    prep_k<<<NV0 / 256, 256>>>(x_feat, mask);
    maskdown_k<<<NV1 / 256, 256>>>(mask);

    wtr_k<<<(27 * 4 * 16 + 255) / 256, 256>>>(w0a, s0a, wt0a, 3, 4, 16);
    wtr_k<<<(27 * 16 * 16 + 255) / 256, 256>>>(w0b, s0b, wt0b, 16, 16, 16);
    wtr_k<<<(27 * 16 * 32 + 255) / 256, 256>>>(wd0, sd0, wtd, 16, 16, 32);
    wtr_k<<<(27 * 32 * 32 + 255) / 256, 256>>>(w1a, s1a, wt1a, 32, 32, 32);
    wtr_k<<<(27 * 32 * 32 + 255) / 256, 256>>>(w1b, s1b, wt1b, 32, 32, 32);

    conv0a_k<<<NV0 / 128, 128>>>(b0a);
    conv0b_k<<<NV0 / 128, 128>>>(b0b);

    conv_dense2_k<16, 2, 128><<<64 * 64, 128>>>(h0b, wtd, bd0, h1a);
    conv_dense2_k<32, 1, 64><<<64 * 64, 128>>>(h1a, wt1a, b1a, h1b);
    conv_dense2_k<32, 1, 64><<<64 * 64, 128>>>(h1b, wt1b, b1b, h1c);

    sample_k<<<(NPTS * 32) / 256, 256>>>(coords, out);
}

// round 7
// speedup vs baseline: 2.4348x; 1.0446x over previous
#include <cuda_runtime.h>

// ---------------------------------------------------------------------------
// SparseConvNet: masked 3D conv stack on 128^3 -> 64^3, then trilinear sample.
//
// This revision: all conv inner loops use packed fp32 FMA (fma.rn.f32x2 ->
// SASS FFMA2), pairing adjacent output channels -> 2x FFMA-pipe throughput.
// prep_k uses warp-aggregated compaction (1 atomic per warp, not per voxel).
// ---------------------------------------------------------------------------

#define D0   128
#define NV0  (D0 * D0 * D0)
#define D1   64
#define NV1  (D1 * D1 * D1)
#define NPTS 65536

typedef unsigned long long u64;

__device__ __forceinline__ u64 pack2(float a) {
    u64 r;
    asm("mov.b64 %0, {%1, %1};" : "=l"(r) : "f"(a));
    return r;
}
__device__ __forceinline__ u64 fma2(u64 a, u64 b, u64 c) {
    u64 d;
    asm("fma.rn.f32x2 %0, %1, %2, %3;" : "=l"(d) : "l"(a), "l"(b), "l"(c));
    return d;
}
__device__ __forceinline__ float2 unpack2(u64 a) {
    float2 f;
    asm("mov.b64 {%0, %1}, %2;" : "=f"(f.x), "=f"(f.y) : "l"(a));
    return f;
}

__device__ float4 g_x0[NV0];
__device__ float  g_h0a[(size_t)NV0 * 16];
__device__ float  g_h0b[(size_t)NV0 * 16];
__device__ float  g_h1a[(size_t)NV1 * 32];
__device__ float  g_h1b[(size_t)NV1 * 32];
__device__ float  g_h1c[(size_t)NV1 * 32];
__device__ float  g_m1[NV1];
__device__ int    g_list0[NV0];
__device__ int    g_n0;

// Pre-transposed weights: [tap][ci][co], bn scale folded, ci zero-padded.
__device__ float g_wt0a[27 * 4 * 16];
__device__ float g_wt0b[27 * 16 * 16];
__device__ float g_wtd [27 * 16 * 32];
__device__ float g_wt1a[27 * 32 * 32];
__device__ float g_wt1b[27 * 32 * 32];

// ---------------------------------------------------------------------------
__global__ void reset_k() {
    if (threadIdx.x == 0) g_n0 = 0;
}

__global__ void prep_k(const float* __restrict__ x, const int* __restrict__ mask) {
    int v = blockIdx.x * blockDim.x + threadIdx.x;
    if (v >= NV0) return;
    int   m  = mask[v];
    float fm = (float)m;
    float a = x[v];
    float b = x[v + NV0];
    float c = x[v + 2 * NV0];
    g_x0[v] = make_float4(a * fm, b * fm, c * fm, 0.f);

    // Warp-aggregated compaction: one atomic per warp.
    unsigned ball = __ballot_sync(0xffffffffu, m != 0);
    int lane = threadIdx.x & 31;
    int base = 0;
    if (lane == 0 && ball) base = atomicAdd(&g_n0, __popc(ball));
    base = __shfl_sync(0xffffffffu, base, 0);
    if (m) g_list0[base + __popc(ball & ((1u << lane) - 1u))] = v;
}

__global__ void maskdown_k(const int* __restrict__ mask) {
    int v = blockIdx.x * blockDim.x + threadIdx.x;
    if (v >= NV1) return;
    int x = v & 63, y = (v >> 6) & 63, z = v >> 12;
    int m = 0;
    for (int dz = 0; dz < 3; dz++) {
        int zi = 2 * z - 1 + dz;
        if ((unsigned)zi >= (unsigned)D0) continue;
        for (int dy = 0; dy < 3; dy++) {
            int yi = 2 * y - 1 + dy;
            if ((unsigned)yi >= (unsigned)D0) continue;
            for (int dx = 0; dx < 3; dx++) {
                int xi = 2 * x - 1 + dx;
                if ((unsigned)xi >= (unsigned)D0) continue;
                if (mask[((size_t)((zi << 7) + yi) << 7) + xi] != 0) m = 1;
            }
        }
    }
    g_m1[v] = (float)m;
}

// Weight transpose + bn-scale fold: dst[tap][ci][co], padded ci -> 0.
__global__ void wtr_k(const float* __restrict__ src, const float* __restrict__ scale,
                      float* __restrict__ dst, int CINR, int CIN, int COUT) {
    int i = blockIdx.x * blockDim.x + threadIdx.x;
    int total = 27 * CIN * COUT;
    if (i >= total) return;
    int co  = i % COUT;
    int rem = i / COUT;
    int ci  = rem % CIN;
    int tap = rem / CIN;
    dst[i] = (ci < CINR) ? src[((size_t)co * CINR + ci) * 27 + tap] * scale[co] : 0.f;
}

// ---------------------------------------------------------------------------
// Sparse conv over the compacted active-voxel list (layer 0), 128^3 DHWC.
// Output channels computed as packed pairs (FFMA2).
// ---------------------------------------------------------------------------
template <int CIN, int COUT>
__device__ __forceinline__ void conv_sparse_body(
    const float* __restrict__ in, const float* __restrict__ wt,
    const float* __restrict__ shift, float* __restrict__ out)
{
    constexpr int NP = COUT / 2;   // packed accumulators
    __shared__ float ws[27 * CIN * COUT];
    __shared__ float ssh[COUT];

    if (blockIdx.x * blockDim.x >= g_n0) return;   // block-uniform early exit

    for (int i = threadIdx.x; i < 27 * CIN * COUT; i += blockDim.x)
        ws[i] = wt[i];
    if (threadIdx.x < COUT) ssh[threadIdx.x] = shift[threadIdx.x];
    __syncthreads();

    int i = blockIdx.x * blockDim.x + threadIdx.x;
    if (i >= g_n0) return;
    int v = g_list0[i];
    int x = v & (D0 - 1), y = (v >> 7) & (D0 - 1), z = v >> 14;

    u64 acc2[NP];
#pragma unroll
    for (int c = 0; c < NP; c++) acc2[c] = 0ull;

#pragma unroll 1
    for (int dz = 0; dz < 3; dz++) {
        int zi = z - 1 + dz;
        if ((unsigned)zi >= (unsigned)D0) continue;
#pragma unroll 1
        for (int dy = 0; dy < 3; dy++) {
            int yi = y - 1 + dy;
            if ((unsigned)yi >= (unsigned)D0) continue;
#pragma unroll 1
            for (int dx = 0; dx < 3; dx++) {
                int xi = x - 1 + dx;
                if ((unsigned)xi >= (unsigned)D0) continue;
                const float4* ip =
                    (const float4*)(in + ((size_t)((zi << 7) + yi) * D0 + xi) * CIN);
                const float* wtap = ws + ((dz * 3 + dy) * 3 + dx) * CIN * COUT;
#pragma unroll
                for (int c4 = 0; c4 < CIN / 4; c4++) {
                    float4 iv = ip[c4];
                    float  a4[4] = {iv.x, iv.y, iv.z, iv.w};
#pragma unroll
                    for (int j = 0; j < 4; j++) {
                        u64 p = pack2(a4[j]);
                        const ulonglong2* wq =
                            (const ulonglong2*)(wtap + (c4 * 4 + j) * COUT);
#pragma unroll
                        for (int g = 0; g < COUT / 4; g++) {
                            ulonglong2 wv = wq[g];
                            acc2[2 * g + 0] = fma2(p, wv.x, acc2[2 * g + 0]);
                            acc2[2 * g + 1] = fma2(p, wv.y, acc2[2 * g + 1]);
                        }
                    }
                }
            }
        }
    }

    float4* op = (float4*)(out + (size_t)v * COUT);
#pragma unroll
    for (int g = 0; g < COUT / 4; g++) {
        float2 f0 = unpack2(acc2[2 * g + 0]);
        float2 f1 = unpack2(acc2[2 * g + 1]);
        float4 r;
        r.x = fmaxf(f0.x + ssh[4 * g + 0], 0.f);
        r.y = fmaxf(f0.y + ssh[4 * g + 1], 0.f);
        r.z = fmaxf(f1.x + ssh[4 * g + 2], 0.f);
        r.w = fmaxf(f1.y + ssh[4 * g + 3], 0.f);
        op[g] = r;
    }
}

__global__ void conv0a_k(const float* shift) {
    conv_sparse_body<4, 16>((const float*)g_x0, g_wt0a, shift, g_h0a);
}
__global__ void conv0b_k(const float* shift) {
    conv_sparse_body<16, 16>(g_h0a, g_wt0b, shift, g_h0b);
}

// ---------------------------------------------------------------------------
// Dense smem-row-staged conv onto the 64^3 grid. COUT=32.
// Block = one output x-row; thread = (x, co-half), 8 packed accumulators.
// Per ci: 3 LDS.32 + 3 pack + 12 LDS.128 + 24 FFMA2 -> FFMA2-pipe-bound.
// ---------------------------------------------------------------------------
template <int CIN, int STRIDE, int DIN>
__global__ void __launch_bounds__(128)
conv_dense2_k(const float* __restrict__ in, const float* __restrict__ wt,
              const float* __restrict__ shift, float* __restrict__ out)
{
    constexpr int DOUT = 64;
    constexpr int COUT = 32;
    constexpr int COH  = 16;
    constexpr int NP   = COH / 2;                    // 8 packed accs
    constexpr int XW   = (STRIDE == 1) ? 66 : 129;
    constexpr int XPAD = (STRIDE == 1) ? 67 : 133;   // coprime-32 pad

    __shared__ float s_in[CIN * XPAD];
    __shared__ float s_w[3 * CIN * COUT];
    __shared__ float s_sh[COUT];

    int b = blockIdx.x;
    int y = b & 63, z = b >> 6;
    int tid = threadIdx.x;
    int x = tid & 63;
    int coh = tid >> 6;
    int coBase = coh * COH;

    if (tid < COUT) s_sh[tid] = shift[tid];

    u64 acc2[NP];
#pragma unroll
    for (int k = 0; k < NP; k++) acc2[k] = 0ull;

#pragma unroll 1
    for (int dz = 0; dz < 3; dz++) {
        int zi = z * STRIDE - 1 + dz;
        if ((unsigned)zi >= (unsigned)DIN) continue;
#pragma unroll 1
        for (int dy = 0; dy < 3; dy++) {
            int yi = y * STRIDE - 1 + dy;
            if ((unsigned)yi >= (unsigned)DIN) continue;   // block-uniform skip

            __syncthreads();
            {
                // Stage input row transposed [ci][x+1], coalesced.
                const float* rp = in + (size_t)(zi * DIN + yi) * DIN * CIN;
                for (int i = tid; i < XW * CIN; i += 128) {
                    int xi = i / CIN - 1;
                    int ci = i & (CIN - 1);
                    float vv = ((unsigned)xi < (unsigned)DIN) ? rp[(size_t)xi * CIN + ci] : 0.f;
                    s_in[ci * XPAD + (xi + 1)] = vv;
                }
                // Stage 3 x-taps of weights (contiguous in [tap][ci][co]).
                const float* wp = wt + (size_t)((dz * 3 + dy) * 3) * CIN * COUT;
                for (int i = tid; i < 3 * CIN * COUT; i += 128) s_w[i] = wp[i];
            }
            __syncthreads();

            int xb = x * STRIDE;
#pragma unroll 4
            for (int ci = 0; ci < CIN; ci++) {
                u64 p0 = pack2(s_in[ci * XPAD + xb + 0]);
                u64 p1 = pack2(s_in[ci * XPAD + xb + 1]);
                u64 p2 = pack2(s_in[ci * XPAD + xb + 2]);
                const ulonglong2* w0 = (const ulonglong2*)(s_w + (0 * CIN + ci) * COUT + coBase);
                const ulonglong2* w1 = (const ulonglong2*)(s_w + (1 * CIN + ci) * COUT + coBase);
                const ulonglong2* w2 = (const ulonglong2*)(s_w + (2 * CIN + ci) * COUT + coBase);
#pragma unroll
                for (int g = 0; g < COH / 4; g++) {
                    ulonglong2 v0 = w0[g], v1 = w1[g], v2 = w2[g];
                    acc2[2 * g + 0] = fma2(p0, v0.x, acc2[2 * g + 0]);
                    acc2[2 * g + 1] = fma2(p0, v0.y, acc2[2 * g + 1]);
                    acc2[2 * g + 0] = fma2(p1, v1.x, acc2[2 * g + 0]);
                    acc2[2 * g + 1] = fma2(p1, v1.y, acc2[2 * g + 1]);
                    acc2[2 * g + 0] = fma2(p2, v2.x, acc2[2 * g + 0]);
                    acc2[2 * g + 1] = fma2(p2, v2.y, acc2[2 * g + 1]);
                }
            }
        }
    }

    size_t v = (size_t)(z * DOUT + y) * DOUT + x;
    float  m = g_m1[v];
    float4* op = (float4*)(out + v * COUT + coBase);
#pragma unroll
    for (int g = 0; g < COH / 4; g++) {
        float2 f0 = unpack2(acc2[2 * g + 0]);
        float2 f1 = unpack2(acc2[2 * g + 1]);
        float4 r;
        r.x = fmaxf(f0.x + s_sh[coBase + 4 * g + 0], 0.f) * m;
        r.y = fmaxf(f0.y + s_sh[coBase + 4 * g + 1], 0.f) * m;
        r.z = fmaxf(f1.x + s_sh[coBase + 4 * g + 2], 0.f) * m;
        r.w = fmaxf(f1.y + s_sh[coBase + 4 * g + 3], 0.f) * m;
        op[g] = r;
    }
}

// ---------------------------------------------------------------------------
// Trilinear sampling: lane = channel (coalesced 128B per corner fetch).
// ---------------------------------------------------------------------------
__global__ void sample_k(const float* __restrict__ coords, float* __restrict__ out) {
    int t = blockIdx.x * blockDim.x + threadIdx.x;
    if (t >= NPTS * 32) return;
    int p = t >> 5, lane = t & 31;

    float cx = coords[3 * p + 0];
    float cy = coords[3 * p + 1];
    float cz = coords[3 * p + 2];
    float fx = (cx + 1.f) * 0.5f * (float)(D1 - 1);
    float fy = (cy + 1.f) * 0.5f * (float)(D1 - 1);
    float fz = (cz + 1.f) * 0.5f * (float)(D1 - 1);
    float x0f = floorf(fx), y0f = floorf(fy), z0f = floorf(fz);
    float tx = fx - x0f, ty = fy - y0f, tz = fz - z0f;
    int x0 = (int)x0f, y0 = (int)y0f, z0 = (int)z0f;

    float acc = 0.f;
#pragma unroll
    for (int dz = 0; dz < 2; dz++) {
#pragma unroll
        for (int dy = 0; dy < 2; dy++) {
#pragma unroll
            for (int dx = 0; dx < 2; dx++) {
                int xi = x0 + dx, yi = y0 + dy, zi = z0 + dz;
                bool valid = (xi >= 0) && (xi < D1) && (yi >= 0) && (yi < D1) &&
                             (zi >= 0) && (zi < D1);
                float wgt = (dx ? tx : 1.f - tx) * (dy ? ty : 1.f - ty) *
                            (dz ? tz : 1.f - tz);
                int xc = min(max(xi, 0), D1 - 1);
                int yc = min(max(yi, 0), D1 - 1);
                int zc = min(max(zi, 0), D1 - 1);
                float val = g_h1c[((size_t)((zc << 6) + yc) * D1 + xc) * 32 + lane];
                acc += val * (valid ? wgt : 0.f);
            }
        }
    }
    out[(size_t)p * 32 + lane] = acc;
}

// ---------------------------------------------------------------------------
extern "C" void kernel_launch(void* const* d_in, const int* in_sizes, int n_in,
                              void* d_out, int out_size) {
    const float* x_feat = (const float*)d_in[0];
    const int*   mask   = (const int*)d_in[1];
    const float* coords = (const float*)d_in[2];
    const float* w0a = (const float*)d_in[3];
    const float* s0a = (const float*)d_in[4];
    const float* b0a = (const float*)d_in[5];
    const float* w0b = (const float*)d_in[6];
    const float* s0b = (const float*)d_in[7];
    const float* b0b = (const float*)d_in[8];
    const float* wd0 = (const float*)d_in[9];
    const float* sd0 = (const float*)d_in[10];
    const float* bd0 = (const float*)d_in[11];
    const float* w1a = (const float*)d_in[12];
    const float* s1a = (const float*)d_in[13];
    const float* b1a = (const float*)d_in[14];
    const float* w1b = (const float*)d_in[15];
    const float* s1b = (const float*)d_in[16];
    const float* b1b = (const float*)d_in[17];
    float* out = (float*)d_out;

    float* wt0a; cudaGetSymbolAddress((void**)&wt0a, g_wt0a);
    float* wt0b; cudaGetSymbolAddress((void**)&wt0b, g_wt0b);
    float* wtd;  cudaGetSymbolAddress((void**)&wtd,  g_wtd);
    float* wt1a; cudaGetSymbolAddress((void**)&wt1a, g_wt1a);
    float* wt1b; cudaGetSymbolAddress((void**)&wt1b, g_wt1b);
    float* h0b;  cudaGetSymbolAddress((void**)&h0b,  g_h0b);
    float* h1a;  cudaGetSymbolAddress((void**)&h1a,  g_h1a);
    float* h1b;  cudaGetSymbolAddress((void**)&h1b,  g_h1b);
    float* h1c;  cudaGetSymbolAddress((void**)&h1c,  g_h1c);

    reset_k<<<1, 32>>>();
    prep_k<<<NV0 / 256, 256>>>(x_feat, mask);
    maskdown_k<<<NV1 / 256, 256>>>(mask);

    wtr_k<<<(27 * 4 * 16 + 255) / 256, 256>>>(w0a, s0a, wt0a, 3, 4, 16);
    wtr_k<<<(27 * 16 * 16 + 255) / 256, 256>>>(w0b, s0b, wt0b, 16, 16, 16);
    wtr_k<<<(27 * 16 * 32 + 255) / 256, 256>>>(wd0, sd0, wtd, 16, 16, 32);
    wtr_k<<<(27 * 32 * 32 + 255) / 256, 256>>>(w1a, s1a, wt1a, 32, 32, 32);
    wtr_k<<<(27 * 32 * 32 + 255) / 256, 256>>>(w1b, s1b, wt1b, 32, 32, 32);

    conv0a_k<<<NV0 / 128, 128>>>(b0a);
    conv0b_k<<<NV0 / 128, 128>>>(b0b);

    conv_dense2_k<16, 2, 128><<<64 * 64, 128>>>(h0b, wtd, bd0, h1a);
    conv_dense2_k<32, 1, 64><<<64 * 64, 128>>>(h1a, wt1a, b1a, h1b);
    conv_dense2_k<32, 1, 64><<<64 * 64, 128>>>(h1b, wt1b, b1b, h1c);

    sample_k<<<(NPTS * 32) / 256, 256>>>(coords, out);
}

// round 16
// speedup vs baseline: 3.3684x; 1.3834x over previous
#include <cuda_runtime.h>
#include <cuda_bf16.h>

// ---------------------------------------------------------------------------
// SparseConvNet on GB300 (plain sm_103 ptxas target -> warp-level mma.sync
// with tf32, NOT tcgen05 and NOT bf16 storage: tf32 keeps rel_err ~4e-4).
//
//   conv0a/b : sparse active-list convs (FFMA2 scalar), 128^3, fp32
//              (conv0b epilogue rounds outputs to tf32-representable fp32)
//   convd    : 16->32 stride-2 implicit GEMM via mma.sync tf32 -> 64^3
//   conv1a/b : 32->32 implicit GEMM via mma.sync tf32
//   sample   : trilinear gather
// ---------------------------------------------------------------------------

#define D0   128
#define NV0  (D0 * D0 * D0)
#define D1   64
#define NV1  (D1 * D1 * D1)
#define NPTS 65536

typedef unsigned int       u32;
typedef unsigned long long u64;

// ---------------- scalar FFMA2 helpers ----------------
__device__ __forceinline__ u64 pack2(float a) {
    u64 r; asm("mov.b64 %0, {%1, %1};" : "=l"(r) : "f"(a)); return r;
}
__device__ __forceinline__ u64 fma2(u64 a, u64 b, u64 c) {
    u64 d; asm("fma.rn.f32x2 %0, %1, %2, %3;" : "=l"(d) : "l"(a), "l"(b), "l"(c)); return d;
}
__device__ __forceinline__ float2 unpack2(u64 a) {
    float2 f; asm("mov.b64 {%0, %1}, %2;" : "=f"(f.x), "=f"(f.y) : "l"(a)); return f;
}

// ---------------- tf32 mma helpers (sm_80+ PTX, valid on plain sm_103) -----
__device__ __forceinline__ float tf32r(float x) {
    u32 r; asm("cvt.rna.tf32.f32 %0, %1;" : "=r"(r) : "f"(x));
    return __uint_as_float(r);
}
__device__ __forceinline__ void mma_tf32(float* d, const u32* a, const u32* b) {
    asm volatile(
        "mma.sync.aligned.m16n8k8.row.col.f32.tf32.tf32.f32 "
        "{%0,%1,%2,%3}, {%4,%5,%6,%7}, {%8,%9}, {%0,%1,%2,%3};"
        : "+f"(d[0]), "+f"(d[1]), "+f"(d[2]), "+f"(d[3])
        : "r"(a[0]), "r"(a[1]), "r"(a[2]), "r"(a[3]), "r"(b[0]), "r"(b[1]));
}

// ---------------- global scratch ----------------
__device__ float4 g_x0[NV0];
__device__ float  g_h0a[(size_t)NV0 * 16];
__device__ float  g_h0b[(size_t)NV0 * 16];    // conv0b out (tf32-rounded fp32)
__device__ float  g_h1a[(size_t)NV1 * 32];    // convd  out (tf32-rounded fp32)
__device__ float  g_h1b[(size_t)NV1 * 32];    // conv1a out (tf32-rounded fp32)
__device__ float  g_h1c[(size_t)NV1 * 32];    // conv1b out (fp32)
__device__ float  g_m1[NV1];
__device__ int    g_list0[NV0];
__device__ int    g_n0;

// fp32 weights [tap][ci][co], bn-scale folded (conv0a/0b)
__device__ float g_wt0a[27 * 4 * 16];
__device__ float g_wt0b[27 * 16 * 16];
// tf32-rounded fp32 weights [tap][co][ci], bn-scale folded (mma layers)
__device__ float g_wmd [27 * 32 * 16];
__device__ float g_wm1a[27 * 32 * 32];
__device__ float g_wm1b[27 * 32 * 32];

// ---------------------------------------------------------------------------
__global__ void reset_k() { if (threadIdx.x == 0) g_n0 = 0; }

__global__ void prep_k(const float* __restrict__ x, const int* __restrict__ mask) {
    int v = blockIdx.x * blockDim.x + threadIdx.x;
    if (v >= NV0) return;
    int   m  = mask[v];
    float fm = (float)m;
    float a = x[v];
    float b = x[v + NV0];
    float c = x[v + 2 * NV0];
    g_x0[v] = make_float4(a * fm, b * fm, c * fm, 0.f);
    unsigned ball = __ballot_sync(0xffffffffu, m != 0);
    int lane = threadIdx.x & 31;
    int base = 0;
    if (lane == 0 && ball) base = atomicAdd(&g_n0, __popc(ball));
    base = __shfl_sync(0xffffffffu, base, 0);
    if (m) g_list0[base + __popc(ball & ((1u << lane) - 1u))] = v;
}

__global__ void maskdown_k(const int* __restrict__ mask) {
    int v = blockIdx.x * blockDim.x + threadIdx.x;
    if (v >= NV1) return;
    int x = v & 63, y = (v >> 6) & 63, z = v >> 12;
    int m = 0;
    for (int dz = 0; dz < 3; dz++) {
        int zi = 2 * z - 1 + dz;
        if ((unsigned)zi >= (unsigned)D0) continue;
        for (int dy = 0; dy < 3; dy++) {
            int yi = 2 * y - 1 + dy;
            if ((unsigned)yi >= (unsigned)D0) continue;
            for (int dx = 0; dx < 3; dx++) {
                int xi = 2 * x - 1 + dx;
                if ((unsigned)xi >= (unsigned)D0) continue;
                if (mask[((size_t)((zi << 7) + yi) << 7) + xi] != 0) m = 1;
            }
        }
    }
    g_m1[v] = (float)m;
}

// fp32 weight transpose + scale fold: dst[tap][ci][co]
__global__ void wtr_k(const float* __restrict__ src, const float* __restrict__ scale,
                      float* __restrict__ dst, int CINR, int CIN, int COUT) {
    int i = blockIdx.x * blockDim.x + threadIdx.x;
    int total = 27 * CIN * COUT;
    if (i >= total) return;
    int co  = i % COUT;
    int rem = i / COUT;
    int ci  = rem % CIN;
    int tap = rem / CIN;
    dst[i] = (ci < CINR) ? src[((size_t)co * CINR + ci) * 27 + tap] * scale[co] : 0.f;
}

// MMA weights: dst[tap][co][ci], bn scale folded, tf32-rounded fp32.
__global__ void wtr_b_k(const float* __restrict__ src, const float* __restrict__ scale,
                        float* __restrict__ dst, int CIN) {
    int i = blockIdx.x * blockDim.x + threadIdx.x;
    if (i >= 27 * 32 * CIN) return;
    int ci  = i % CIN;
    int co  = (i / CIN) % 32;
    int tap = i / (CIN * 32);
    dst[((size_t)tap * 32 + co) * CIN + ci] =
        tf32r(src[((size_t)co * CIN + ci) * 27 + tap] * scale[co]);
}

// ---------------------------------------------------------------------------
// Sparse conv over the active list (layer 0), 128^3 DHWC, FFMA2.
// ROUND: round outputs to tf32-representable fp32 (feeding an MMA layer).
// ---------------------------------------------------------------------------
template <int CIN, int COUT, bool ROUND>
__device__ __forceinline__ void conv_sparse_body(
    const float* __restrict__ in, const float* __restrict__ wt,
    const float* __restrict__ shift, float* __restrict__ out)
{
    constexpr int NP = COUT / 2;
    __shared__ float ws[27 * CIN * COUT];
    __shared__ float ssh[COUT];

    if (blockIdx.x * blockDim.x >= g_n0) return;

    for (int i = threadIdx.x; i < 27 * CIN * COUT; i += blockDim.x) ws[i] = wt[i];
    if (threadIdx.x < COUT) ssh[threadIdx.x] = shift[threadIdx.x];
    __syncthreads();

    int i = blockIdx.x * blockDim.x + threadIdx.x;
    if (i >= g_n0) return;
    int v = g_list0[i];
    int x = v & (D0 - 1), y = (v >> 7) & (D0 - 1), z = v >> 14;

    u64 acc2[NP];
#pragma unroll
    for (int c = 0; c < NP; c++) acc2[c] = 0ull;

#pragma unroll 1
    for (int dz = 0; dz < 3; dz++) {
        int zi = z - 1 + dz;
        if ((unsigned)zi >= (unsigned)D0) continue;
#pragma unroll 1
        for (int dy = 0; dy < 3; dy++) {
            int yi = y - 1 + dy;
            if ((unsigned)yi >= (unsigned)D0) continue;
#pragma unroll 1
            for (int dx = 0; dx < 3; dx++) {
                int xi = x - 1 + dx;
                if ((unsigned)xi >= (unsigned)D0) continue;
                const float4* ip =
                    (const float4*)(in + ((size_t)((zi << 7) + yi) * D0 + xi) * CIN);
                const float* wtap = ws + ((dz * 3 + dy) * 3 + dx) * CIN * COUT;
#pragma unroll
                for (int c4 = 0; c4 < CIN / 4; c4++) {
                    float4 iv = ip[c4];
                    float  a4[4] = {iv.x, iv.y, iv.z, iv.w};
#pragma unroll
                    for (int j = 0; j < 4; j++) {
                        u64 p = pack2(a4[j]);
                        const ulonglong2* wq =
                            (const ulonglong2*)(wtap + (c4 * 4 + j) * COUT);
#pragma unroll
                        for (int g = 0; g < COUT / 4; g++) {
                            ulonglong2 wv = wq[g];
                            acc2[2 * g + 0] = fma2(p, wv.x, acc2[2 * g + 0]);
                            acc2[2 * g + 1] = fma2(p, wv.y, acc2[2 * g + 1]);
                        }
                    }
                }
            }
        }
    }

    float4* op = (float4*)(out + (size_t)v * COUT);
#pragma unroll
    for (int g = 0; g < COUT / 4; g++) {
        float2 f0 = unpack2(acc2[2 * g + 0]);
        float2 f1 = unpack2(acc2[2 * g + 1]);
        float4 r;
        r.x = fmaxf(f0.x + ssh[4 * g + 0], 0.f);
        r.y = fmaxf(f0.y + ssh[4 * g + 1], 0.f);
        r.z = fmaxf(f1.x + ssh[4 * g + 2], 0.f);
        r.w = fmaxf(f1.y + ssh[4 * g + 3], 0.f);
        if (ROUND) { r.x = tf32r(r.x); r.y = tf32r(r.y); r.z = tf32r(r.z); r.w = tf32r(r.w); }
        op[g] = r;
    }
}

__global__ void conv0a_k(const float* shift) {
    conv_sparse_body<4, 16, false>((const float*)g_x0, g_wt0a, shift, g_h0a);
}
__global__ void conv0b_k(const float* shift) {
    conv_sparse_body<16, 16, true>(g_h0a, g_wt0b, shift, g_h0b);
}

// ---------------------------------------------------------------------------
// Implicit-GEMM conv via warp-level mma.sync tf32 (fp32 storage, fp32 accum).
// CTA = 128 output voxels (z fixed, 2 y-rows x 64 x) x 32 couts, 4 warps.
// Warp: M=32 voxels (2 m16 tiles) x N=32 (4 n8 tiles), K=CIN per tap (k8
// steps). Smem pitch CIN+4 floats (== 4 mod 32) -> all fragment LDS.32 and
// staging STS.128 are bank-conflict-free. Boundary taps stage zeros.
//
// m16n8k8 tf32 fragment layout (gid = lane>>2, tig = lane&3):
//   A: a0=(gid,tig) a1=(gid+8,tig) a2=(gid,tig+4) a3=(gid+8,tig+4)
//   B: b0=(k=tig, n=gid) b1=(k=tig+4, n=gid)
//   C: c0=(gid,2tig) c1=(gid,2tig+1) c2=(gid+8,2tig) c3=(gid+8,2tig+1)
// ---------------------------------------------------------------------------
template <int CIN, int STRIDE, int DIN, bool ROUND>
__global__ void __launch_bounds__(128)
conv_mma_k(const float* __restrict__ in,    // [DIN^3][CIN] fp32 DHWC (tf32-repr)
           const float* __restrict__ wt,    // [27][32co][CIN] fp32 (tf32-repr)
           const float* __restrict__ shift, float* __restrict__ out)
{
    constexpr int PITCH  = CIN + 4;          // floats
    constexpr int KSTEPS = CIN / 8;

    __shared__ __align__(16) float sA[128 * PITCH];
    __shared__ __align__(16) float sB[32 * PITCH];
    __shared__ float s_sh[32];

    int tid = threadIdx.x, lane = tid & 31, warp = tid >> 5;
    int bx = blockIdx.x;
    int z = bx >> 5, y0 = (bx & 31) << 1;
    int h = tid >> 6, x = tid & 63;
    int gid = lane >> 2, tig = lane & 3;

    if (tid < 32) s_sh[tid] = shift[tid];

    float d[2][4][4];
#pragma unroll
    for (int mt = 0; mt < 2; mt++)
#pragma unroll
        for (int nt = 0; nt < 4; nt++)
#pragma unroll
            for (int k = 0; k < 4; k++) d[mt][nt][k] = 0.f;

#pragma unroll 1
    for (int dz = 0; dz < 3; dz++) {
        int zi = z * STRIDE + dz - 1;
        if ((unsigned)zi >= (unsigned)DIN) continue;   // block-uniform skip
#pragma unroll 1
        for (int dy = 0; dy < 3; dy++) {
            int yi = (y0 + h) * STRIDE + dy - 1;
            bool yok = (unsigned)yi < (unsigned)DIN;
            int  yc  = yok ? yi : 0;
#pragma unroll 1
            for (int dx = 0; dx < 3; dx++) {
                int xi = x * STRIDE + dx - 1;
                bool ok = yok && ((unsigned)xi < (unsigned)DIN);
                int  xc = ((unsigned)xi < (unsigned)DIN) ? xi : 0;
                int  tap = (dz * 3 + dy) * 3 + dx;

                __syncthreads();   // prior tap's fragment loads complete

                // Stage A row m = tid: CIN floats = CIN/4 x float4, zero OOB.
                const float4* src =
                    (const float4*)(in + ((size_t)(zi * DIN + yc) * DIN + xc) * CIN);
#pragma unroll
                for (int c = 0; c < CIN / 4; c++) {
                    float4 val = ok ? src[c] : make_float4(0.f, 0.f, 0.f, 0.f);
                    *(float4*)(sA + tid * PITCH + c * 4) = val;
                }
                // Stage B tap: 32 co x CIN floats (contiguous copy).
                {
                    const float4* wp = (const float4*)(wt + (size_t)tap * 32 * CIN);
#pragma unroll
                    for (int i = tid; i < 32 * CIN / 4; i += 128) {
                        int co = i / (CIN / 4), ch = i % (CIN / 4);
                        *(float4*)(sB + co * PITCH + ch * 4) = wp[i];
                    }
                }
                __syncthreads();

#pragma unroll
                for (int ks = 0; ks < KSTEPS; ks++) {
                    u32 af[2][4];
#pragma unroll
                    for (int mt = 0; mt < 2; mt++) {
                        int r0 = warp * 32 + mt * 16 + gid;
                        af[mt][0] = __float_as_uint(sA[(r0 + 0) * PITCH + ks * 8 + tig + 0]);
                        af[mt][1] = __float_as_uint(sA[(r0 + 8) * PITCH + ks * 8 + tig + 0]);
                        af[mt][2] = __float_as_uint(sA[(r0 + 0) * PITCH + ks * 8 + tig + 4]);
                        af[mt][3] = __float_as_uint(sA[(r0 + 8) * PITCH + ks * 8 + tig + 4]);
                    }
                    u32 bf[4][2];
#pragma unroll
                    for (int nt = 0; nt < 4; nt++) {
                        bf[nt][0] = __float_as_uint(sB[(nt * 8 + gid) * PITCH + ks * 8 + tig + 0]);
                        bf[nt][1] = __float_as_uint(sB[(nt * 8 + gid) * PITCH + ks * 8 + tig + 4]);
                    }
#pragma unroll
                    for (int mt = 0; mt < 2; mt++)
#pragma unroll
                        for (int nt = 0; nt < 4; nt++)
                            mma_tf32(d[mt][nt], af[mt], bf[nt]);
                }
            }
        }
    }

    // Epilogue: relu(acc + shift) * m1, optional tf32 rounding, DHWC store.
#pragma unroll
    for (int mt = 0; mt < 2; mt++) {
#pragma unroll
        for (int nt = 0; nt < 4; nt++) {
            int c = nt * 8 + tig * 2;
            float sh0 = s_sh[c + 0], sh1 = s_sh[c + 1];
#pragma unroll
            for (int half = 0; half < 2; half++) {
                int r = warp * 32 + mt * 16 + gid + half * 8;
                int yy = y0 + (r >> 6), xx = r & 63;
                size_t v = (size_t)((z * 64 + yy) * 64 + xx);
                float mm = g_m1[v];
                float o0 = fmaxf(d[mt][nt][half * 2 + 0] + sh0, 0.f) * mm;
                float o1 = fmaxf(d[mt][nt][half * 2 + 1] + sh1, 0.f) * mm;
                if (ROUND) { o0 = tf32r(o0); o1 = tf32r(o1); }
                *(float2*)(out + v * 32 + c) = make_float2(o0, o1);
            }
        }
    }
}

// ---------------------------------------------------------------------------
// Trilinear sampling: lane = channel.
// ---------------------------------------------------------------------------
__global__ void sample_k(const float* __restrict__ coords, float* __restrict__ out) {
    int t = blockIdx.x * blockDim.x + threadIdx.x;
    if (t >= NPTS * 32) return;
    int p = t >> 5, lane = t & 31;

    float cx = coords[3 * p + 0];
    float cy = coords[3 * p + 1];
    float cz = coords[3 * p + 2];
    float fx = (cx + 1.f) * 0.5f * (float)(D1 - 1);
    float fy = (cy + 1.f) * 0.5f * (float)(D1 - 1);
    float fz = (cz + 1.f) * 0.5f * (float)(D1 - 1);
    float x0f = floorf(fx), y0f = floorf(fy), z0f = floorf(fz);
    float tx = fx - x0f, ty = fy - y0f, tz = fz - z0f;
    int x0 = (int)x0f, y0 = (int)y0f, z0 = (int)z0f;

    float acc = 0.f;
#pragma unroll
    for (int dz = 0; dz < 2; dz++) {
#pragma unroll
        for (int dy = 0; dy < 2; dy++) {
#pragma unroll
            for (int dx = 0; dx < 2; dx++) {
                int xi = x0 + dx, yi = y0 + dy, zi = z0 + dz;
                bool valid = (xi >= 0) && (xi < D1) && (yi >= 0) && (yi < D1) &&
                             (zi >= 0) && (zi < D1);
                float wgt = (dx ? tx : 1.f - tx) * (dy ? ty : 1.f - ty) *
                            (dz ? tz : 1.f - tz);
                int xc = min(max(xi, 0), D1 - 1);
                int yc = min(max(yi, 0), D1 - 1);
                int zc = min(max(zi, 0), D1 - 1);
                float val = g_h1c[((size_t)((zc << 6) + yc) * D1 + xc) * 32 + lane];
                acc += val * (valid ? wgt : 0.f);
            }
        }
    }
    out[(size_t)p * 32 + lane] = acc;
}

// ---------------------------------------------------------------------------
extern "C" void kernel_launch(void* const* d_in, const int* in_sizes, int n_in,
                              void* d_out, int out_size) {
    const float* x_feat = (const float*)d_in[0];
    const int*   mask   = (const int*)d_in[1];
    const float* coords = (const float*)d_in[2];
    const float* w0a = (const float*)d_in[3];
    const float* s0a = (const float*)d_in[4];
    const float* b0a = (const float*)d_in[5];
    const float* w0b = (const float*)d_in[6];
    const float* s0b = (const float*)d_in[7];
    const float* b0b = (const float*)d_in[8];
    const float* wd0 = (const float*)d_in[9];
    const float* sd0 = (const float*)d_in[10];
    const float* bd0 = (const float*)d_in[11];
    const float* w1a = (const float*)d_in[12];
    const float* s1a = (const float*)d_in[13];
    const float* b1a = (const float*)d_in[14];
    const float* w1b = (const float*)d_in[15];
    const float* s1b = (const float*)d_in[16];
    const float* b1b = (const float*)d_in[17];
    float* out = (float*)d_out;

    float* wt0a; cudaGetSymbolAddress((void**)&wt0a, g_wt0a);
    float* wt0b; cudaGetSymbolAddress((void**)&wt0b, g_wt0b);
    float* wmd;  cudaGetSymbolAddress((void**)&wmd,  g_wmd);
    float* wm1a; cudaGetSymbolAddress((void**)&wm1a, g_wm1a);
    float* wm1b; cudaGetSymbolAddress((void**)&wm1b, g_wm1b);
    float* h0b;  cudaGetSymbolAddress((void**)&h0b,  g_h0b);
    float* h1a;  cudaGetSymbolAddress((void**)&h1a,  g_h1a);
    float* h1b;  cudaGetSymbolAddress((void**)&h1b,  g_h1b);
    float* h1c;  cudaGetSymbolAddress((void**)&h1c,  g_h1c);

    reset_k<<<1, 32>>>();
    prep_k<<<NV0 / 256, 256>>>(x_feat, mask);
    maskdown_k<<<NV1 / 256, 256>>>(mask);

    wtr_k<<<(27 * 4 * 16 + 255) / 256, 256>>>(w0a, s0a, wt0a, 3, 4, 16);
    wtr_k<<<(27 * 16 * 16 + 255) / 256, 256>>>(w0b, s0b, wt0b, 16, 16, 16);
    wtr_b_k<<<(27 * 32 * 16 + 255) / 256, 256>>>(wd0, sd0, wmd, 16);
    wtr_b_k<<<(27 * 32 * 32 + 255) / 256, 256>>>(w1a, s1a, wm1a, 32);
    wtr_b_k<<<(27 * 32 * 32 + 255) / 256, 256>>>(w1b, s1b, wm1b, 32);

    conv0a_k<<<NV0 / 128, 128>>>(b0a);
    conv0b_k<<<NV0 / 128, 128>>>(b0b);

    conv_mma_k<16, 2, 128, true ><<<64 * 32, 128>>>(h0b, wmd, bd0, h1a);
    conv_mma_k<32, 1, 64,  true ><<<64 * 32, 128>>>(h1a, wm1a, b1a, h1b);
    conv_mma_k<32, 1, 64,  false><<<64 * 32, 128>>>(h1b, wm1b, b1b, h1c);

    sample_k<<<(NPTS * 32) / 256, 256>>>(coords, out);
}